// round 1
// baseline (speedup 1.0000x reference)
#include <cuda_runtime.h>

// Fixed problem shape (GNNReachabilityNet): N=100000 nodes, E=1600000 edges, G=64 graphs.
#define NMAX 100352
#define GMAX 64

struct Params {
    float p1[11], q1[11], p2[11], q2[11];
    float ps, qs, s0, t0, b2, bo;
};

__device__ Params  gP;
__device__ float4  g_agg[NMAX];     // (sum alpha, sum beta, deg, 0)
__device__ float4  g_xdots[NMAX];   // (alpha=x.p2, beta=x.q2, gamma=x.p1, delta=x.q1)
__device__ float   g_s[NMAX];       // s[u] = xv[u] . wf
__device__ float   g_aggs[NMAX];    // sum of s[src] over incoming edges
__device__ unsigned g_outmax[GMAX]; // order-encoded float max
__device__ int     g_flag;          // 1 = indices are int64, 0 = int32

__device__ __forceinline__ unsigned enc_f(float f) {
    unsigned u = __float_as_uint(f);
    return (u & 0x80000000u) ? ~u : (u | 0x80000000u);
}
__device__ __forceinline__ float dec_f(unsigned e) {
    return (e & 0x80000000u) ? __uint_as_float(e ^ 0x80000000u) : __uint_as_float(~e);
}
#define ENC_NEG_INF 0x007FFFFFu  // enc(-inf)

// ---------------------------------------------------------------------------
// K0: detect whether edge_index/batch are int64 (JAX x64 on) or int32 (default).
// For int64 little-endian nonneg values < 2^31, every odd int32 word is 0.
// For int32 random node ids in [0,100000), odd words are ~always nonzero.
// ---------------------------------------------------------------------------
__global__ void k_detect(const unsigned* ei_words) {
    if (threadIdx.x == 0 && blockIdx.x == 0) {
        int nz = 0;
        for (int i = 0; i < 256; i++)
            if (ei_words[2 * i + 1] != 0u) nz++;
        g_flag = (nz == 0) ? 1 : 0;
    }
}

// ---------------------------------------------------------------------------
// K1: zero scratch
// ---------------------------------------------------------------------------
__global__ void k_zero(int n) {
    int i = blockIdx.x * blockDim.x + threadIdx.x;
    if (i < n) {
        g_agg[i]  = make_float4(0.f, 0.f, 0.f, 0.f);
        g_aggs[i] = 0.f;
    }
    if (i < GMAX) g_outmax[i] = ENC_NEG_INF;
}

// ---------------------------------------------------------------------------
// K2: fold all weight matrices down to four 11-vectors + 6 scalars.
// Math (deg>=1, inv = 1/deg):
//   h1 = x@M1 + agg_xn@M2 + c1,  M1 = Wv@Wa + Pc, M2 = Wv@Wb + Pd,
//        c1 = be1 + bv@Wa + bv@Wb  (Wa/Wb = We1 rows 0:64/64:128, Pc/Pd = rows 128:130/130:132 at x-cols 9,10)
//   xv = x@A1 + agg_xn@A2 + c2,  A1 = M1@Wx, A2 = M2@Wx, c2 = c1@Wx + bx
//   node_out = xv.we + inv*sum_src(xv[src].wf) + b2,
//        we = We2[0:64]@Wo, wf = We2[64:128]@Wo, b2 = be2@Wo + bo
//   => per-node scalars via p1=A1@wf, q1=A1@we, p2=A2@wf, q2=A2@we,
//      ps=c2.wf, qs=c2.we, s0=bx.wf, t0=bx.we.
// deg==0: h-sums are empty => xv = bx (hence s0/t0), node_out = bo.
// ---------------------------------------------------------------------------
__global__ void k_fold(const float* Wv, const float* bv,
                       const float* We1, const float* be1,
                       const float* Wx,  const float* bx,
                       const float* We2, const float* be2,
                       const float* Wo,  const float* bo) {
    __shared__ float M1[11 * 128], M2[11 * 128];
    __shared__ float A1[11 * 64],  A2[11 * 64];
    __shared__ float c1[128], c2[64], wev[64], wfv[64];
    int t = threadIdx.x; // 256 threads, 1 block

    for (int idx = t; idx < 11 * 128; idx += 256) {
        int i = idx / 128, m = idx % 128;
        double a1 = 0.0, a2 = 0.0;
        for (int k = 0; k < 64; k++) {
            double wk = Wv[i * 64 + k];
            a1 += wk * (double)We1[k * 128 + m];
            a2 += wk * (double)We1[(64 + k) * 128 + m];
        }
        if (i == 9)  { a1 += We1[128 * 128 + m]; a2 += We1[130 * 128 + m]; }
        if (i == 10) { a1 += We1[129 * 128 + m]; a2 += We1[131 * 128 + m]; }
        M1[idx] = (float)a1; M2[idx] = (float)a2;
    }
    for (int m = t; m < 128; m += 256) {
        double c = be1[m];
        for (int k = 0; k < 64; k++)
            c += (double)bv[k] * ((double)We1[k * 128 + m] + (double)We1[(64 + k) * 128 + m]);
        c1[m] = (float)c;
    }
    for (int j = t; j < 64; j += 256) {
        double a = 0.0, b = 0.0;
        for (int o = 0; o < 64; o++) {
            a += (double)We2[j * 64 + o]        * (double)Wo[o];
            b += (double)We2[(64 + j) * 64 + o] * (double)Wo[o];
        }
        wev[j] = (float)a; wfv[j] = (float)b;
    }
    __syncthreads();
    for (int idx = t; idx < 11 * 64; idx += 256) {
        int i = idx / 64, o = idx % 64;
        double a1 = 0.0, a2 = 0.0;
        for (int m = 0; m < 128; m++) {
            double wx = Wx[m * 64 + o];
            a1 += (double)M1[i * 128 + m] * wx;
            a2 += (double)M2[i * 128 + m] * wx;
        }
        A1[idx] = (float)a1; A2[idx] = (float)a2;
    }
    for (int o = t; o < 64; o += 256) {
        double c = bx[o];
        for (int m = 0; m < 128; m++) c += (double)c1[m] * (double)Wx[m * 64 + o];
        c2[o] = (float)c;
    }
    __syncthreads();
    if (t < 11) {
        int i = t;
        double a = 0, b = 0, g = 0, d = 0;
        for (int o = 0; o < 64; o++) {
            a += (double)A2[i * 64 + o] * (double)wfv[o]; // p2
            b += (double)A2[i * 64 + o] * (double)wev[o]; // q2
            g += (double)A1[i * 64 + o] * (double)wfv[o]; // p1
            d += (double)A1[i * 64 + o] * (double)wev[o]; // q1
        }
        gP.p2[i] = (float)a; gP.q2[i] = (float)b;
        gP.p1[i] = (float)g; gP.q1[i] = (float)d;
    }
    if (t == 32) {
        double ps = 0, qs = 0, s0 = 0, t0 = 0, b2 = 0;
        for (int o = 0; o < 64; o++) {
            ps += (double)c2[o] * (double)wfv[o];
            qs += (double)c2[o] * (double)wev[o];
            s0 += (double)bx[o] * (double)wfv[o];
            t0 += (double)bx[o] * (double)wev[o];
            b2 += (double)be2[o] * (double)Wo[o];
        }
        gP.ps = (float)ps; gP.qs = (float)qs;
        gP.s0 = (float)s0; gP.t0 = (float)t0;
        gP.b2 = (float)(b2 + (double)bo[0]);
        gP.bo = bo[0];
    }
}

// ---------------------------------------------------------------------------
// K3: per-node 11-dim dots against the four folded vectors
// ---------------------------------------------------------------------------
__global__ void k_dots(const float* __restrict__ x, int n) {
    int v = blockIdx.x * blockDim.x + threadIdx.x;
    if (v >= n) return;
    float a = 0.f, b = 0.f, g = 0.f, d = 0.f;
#pragma unroll
    for (int i = 0; i < 11; i++) {
        float xv = __ldg(&x[v * 11 + i]);
        a += xv * gP.p2[i];
        b += xv * gP.q2[i];
        g += xv * gP.p1[i];
        d += xv * gP.q1[i];
    }
    g_xdots[v] = make_float4(a, b, g, d);
}

// ---------------------------------------------------------------------------
// K4: edge pass 1 — one float4 RED per edge: agg[dst] += (alpha[src], beta[src], 1, 0)
// ---------------------------------------------------------------------------
__global__ void k_edge1(const void* __restrict__ ei, int E) {
    int e = blockIdx.x * blockDim.x + threadIdx.x;
    if (e >= E) return;
    int s, d;
    if (g_flag) {
        const long long* p = (const long long*)ei;
        s = (int)p[e]; d = (int)p[E + e];
    } else {
        const int* p = (const int*)ei;
        s = p[e]; d = p[E + e];
    }
    float2 ab = *(const float2*)&g_xdots[s];
    atomicAdd(&g_agg[d], make_float4(ab.x, ab.y, 1.f, 0.f));
}

// ---------------------------------------------------------------------------
// K5: per-node s = gamma + inv*sum(alpha) + ps  (deg>0), else s0
// ---------------------------------------------------------------------------
__global__ void k_nodes(int n) {
    int v = blockIdx.x * blockDim.x + threadIdx.x;
    if (v >= n) return;
    float4 ag = g_agg[v];
    float4 xd = g_xdots[v];
    float s;
    if (ag.z > 0.f) {
        float inv = 1.f / ag.z;
        s = xd.z + inv * ag.x + gP.ps;
    } else {
        s = gP.s0;
    }
    g_s[v] = s;
}

// ---------------------------------------------------------------------------
// K6: edge pass 2 — one scalar RED per edge: aggs[dst] += s[src]
// ---------------------------------------------------------------------------
__global__ void k_edge2(const void* __restrict__ ei, int E) {
    int e = blockIdx.x * blockDim.x + threadIdx.x;
    if (e >= E) return;
    int s, d;
    if (g_flag) {
        const long long* p = (const long long*)ei;
        s = (int)p[e]; d = (int)p[E + e];
    } else {
        const int* p = (const int*)ei;
        s = p[e]; d = p[E + e];
    }
    atomicAdd(&g_aggs[d], g_s[s]);
}

// ---------------------------------------------------------------------------
// K7: node_out + block-local segment max + global atomicMax (encoded)
// ---------------------------------------------------------------------------
__global__ void k_final(const void* __restrict__ batch, int n) {
    __shared__ unsigned sm[GMAX];
    int t = threadIdx.x;
    if (t < GMAX) sm[t] = ENC_NEG_INF;
    __syncthreads();
    int v = blockIdx.x * blockDim.x + t;
    if (v < n) {
        float deg = g_agg[v].z;
        float no;
        if (deg > 0.f) {
            float inv = 1.f / deg;
            float4 xd = g_xdots[v];
            float tt = xd.w + inv * g_agg[v].y + gP.qs;  // t[v]
            no = tt + inv * g_aggs[v] + gP.b2;
        } else {
            no = gP.bo;
        }
        int g = g_flag ? (int)((const long long*)batch)[v] : ((const int*)batch)[v];
        atomicMax(&sm[g], enc_f(no));
    }
    __syncthreads();
    if (t < GMAX && sm[t] != ENC_NEG_INF) atomicMax(&g_outmax[t], sm[t]);
}

// ---------------------------------------------------------------------------
// K8: decode out
// ---------------------------------------------------------------------------
__global__ void k_writeout(float* out, int g) {
    int i = threadIdx.x;
    if (i < g) out[i] = dec_f(g_outmax[i]);
}

extern "C" void kernel_launch(void* const* d_in, const int* in_sizes, int n_in,
                              void* d_out, int out_size) {
    const float* x    = (const float*)d_in[0];
    const void*  ei   = d_in[1];
    const void*  batch = d_in[2];
    const float* Wv  = (const float*)d_in[3];
    const float* bv  = (const float*)d_in[4];
    const float* We1 = (const float*)d_in[5];
    const float* be1 = (const float*)d_in[6];
    const float* Wx  = (const float*)d_in[7];
    const float* bx  = (const float*)d_in[8];
    const float* We2 = (const float*)d_in[9];
    const float* be2 = (const float*)d_in[10];
    const float* Wo  = (const float*)d_in[11];
    const float* bo  = (const float*)d_in[12];
    float* out = (float*)d_out;

    int n = in_sizes[0] / 11;          // 100000
    int E = in_sizes[1] / 2;           // 1600000 (element count is dtype-agnostic /2)
    if (n > NMAX) n = NMAX;

    const int TPB = 256;
    int nb_n = (n + TPB - 1) / TPB;
    int nb_e = (E + TPB - 1) / TPB;

    k_detect<<<1, 32>>>((const unsigned*)ei);
    k_zero<<<nb_n, TPB>>>(n);
    k_fold<<<1, 256>>>(Wv, bv, We1, be1, Wx, bx, We2, be2, Wo, bo);
    k_dots<<<nb_n, TPB>>>(x, n);
    k_edge1<<<nb_e, TPB>>>(ei, E);
    k_nodes<<<nb_n, TPB>>>(n);
    k_edge2<<<nb_e, TPB>>>(ei, E);
    k_final<<<nb_n, TPB>>>(batch, n);
    k_writeout<<<1, 64>>>(out, out_size);
}

// round 3
// speedup vs baseline: 1.4095x; 1.4095x over previous
#include <cuda_runtime.h>

// Fixed problem shape (GNNReachabilityNet): N=100000 nodes, E=1600000 edges, G=64 graphs.
#define NMAX  100352
#define GMAX  64
#define EMAXH 800000   // max edges / 2

struct Params {
    float p1[11], q1[11], p2[11], q2[11];
    float ps, qs, s0, t0, b2, bo;
};

__device__ Params   gP;
__device__ float    g_alpha[NMAX];   // alpha = x.p2 (gathered in pass 1)
__device__ float2   g_bg[NMAX];      // (beta = x.q2, gamma = x.p1)
__device__ float    g_delta[NMAX];   // delta = x.q1
__device__ float2   g_agg[NMAX];     // (sum alpha over incoming, deg)
__device__ float    g_w[NMAX];       // w[u] = beta[u] + s[u]  (gathered in pass 2)
__device__ float    g_aggs[NMAX];    // sum of w[src] over incoming edges
__device__ int4     g_eidx[EMAXH];   // packed (s0,d0,s1,d1) per edge pair
__device__ unsigned g_outmax[GMAX];  // order-encoded float max
__device__ int      g_flag;          // 1 = indices are int64, 0 = int32

__device__ __forceinline__ unsigned enc_f(float f) {
    unsigned u = __float_as_uint(f);
    return (u & 0x80000000u) ? ~u : (u | 0x80000000u);
}
__device__ __forceinline__ float dec_f(unsigned e) {
    return (e & 0x80000000u) ? __uint_as_float(e ^ 0x80000000u) : __uint_as_float(~e);
}
#define ENC_NEG_INF 0x007FFFFFu  // enc(-inf)

// ---------------------------------------------------------------------------
// K1: fold all weight matrices down to four 11-vectors + 6 scalars (fp32 is
// plenty: rel_err margin ~2000x). Also detects int64-vs-int32 indices.
//   node_out = delta + qs + b2 + inv * sum_incoming(beta[src] + s[src])
//   s[u] = gamma[u] + inv_u*sum(alpha) + ps (deg_u>0) else s0
// ---------------------------------------------------------------------------
__global__ void k_fold(const float* Wv, const float* bv,
                       const float* We1, const float* be1,
                       const float* Wx,  const float* bx,
                       const float* We2, const float* be2,
                       const float* Wo,  const float* bo,
                       const unsigned* ei_words) {
    __shared__ float M1[11 * 128], M2[11 * 128];
    __shared__ float A1[11 * 64],  A2[11 * 64];
    __shared__ float c1[128], c2[64], wev[64], wfv[64];
    int t = threadIdx.x; // 256 threads, 1 block

    if (t == 0) {
        // int64 little-endian nonneg < 2^31 => all odd words zero.
        int nz = 0;
        for (int i = 0; i < 256; i++)
            if (ei_words[2 * i + 1] != 0u) nz++;
        g_flag = (nz == 0) ? 1 : 0;
    }

    for (int idx = t; idx < 11 * 128; idx += 256) {
        int i = idx / 128, m = idx % 128;
        float a1 = 0.f, a2 = 0.f;
        for (int k = 0; k < 64; k++) {
            float wk = Wv[i * 64 + k];
            a1 += wk * We1[k * 128 + m];
            a2 += wk * We1[(64 + k) * 128 + m];
        }
        if (i == 9)  { a1 += We1[128 * 128 + m]; a2 += We1[130 * 128 + m]; }
        if (i == 10) { a1 += We1[129 * 128 + m]; a2 += We1[131 * 128 + m]; }
        M1[idx] = a1; M2[idx] = a2;
    }
    for (int m = t; m < 128; m += 256) {
        float c = be1[m];
        for (int k = 0; k < 64; k++)
            c += bv[k] * (We1[k * 128 + m] + We1[(64 + k) * 128 + m]);
        c1[m] = c;
    }
    for (int j = t; j < 64; j += 256) {
        float a = 0.f, b = 0.f;
        for (int o = 0; o < 64; o++) {
            a += We2[j * 64 + o]        * Wo[o];
            b += We2[(64 + j) * 64 + o] * Wo[o];
        }
        wev[j] = a; wfv[j] = b;
    }
    __syncthreads();
    for (int idx = t; idx < 11 * 64; idx += 256) {
        int i = idx / 64, o = idx % 64;
        float a1 = 0.f, a2 = 0.f;
        for (int m = 0; m < 128; m++) {
            float wx = Wx[m * 64 + o];
            a1 += M1[i * 128 + m] * wx;
            a2 += M2[i * 128 + m] * wx;
        }
        A1[idx] = a1; A2[idx] = a2;
    }
    for (int o = t; o < 64; o += 256) {
        float c = bx[o];
        for (int m = 0; m < 128; m++) c += c1[m] * Wx[m * 64 + o];
        c2[o] = c;
    }
    __syncthreads();
    if (t < 11) {
        int i = t;
        float a = 0.f, b = 0.f, g = 0.f, d = 0.f;
        for (int o = 0; o < 64; o++) {
            a += A2[i * 64 + o] * wfv[o]; // p2 -> alpha
            b += A2[i * 64 + o] * wev[o]; // q2 -> beta
            g += A1[i * 64 + o] * wfv[o]; // p1 -> gamma
            d += A1[i * 64 + o] * wev[o]; // q1 -> delta
        }
        gP.p2[i] = a; gP.q2[i] = b;
        gP.p1[i] = g; gP.q1[i] = d;
    }
    if (t == 32) {
        float ps = 0.f, qs = 0.f, s0 = 0.f, t0 = 0.f, b2 = 0.f;
        for (int o = 0; o < 64; o++) {
            ps += c2[o] * wfv[o];
            qs += c2[o] * wev[o];
            s0 += bx[o] * wfv[o];
            t0 += bx[o] * wev[o];
            b2 += be2[o] * Wo[o];
        }
        gP.ps = ps; gP.qs = qs;
        gP.s0 = s0; gP.t0 = t0;
        gP.b2 = b2 + bo[0];
        gP.bo = bo[0];
    }
}

// ---------------------------------------------------------------------------
// K2: per-node 11-dim dots; x staged through shared memory (coalesced float4),
// also zeroes all per-node accumulators and the output max array.
// Tile = 256 nodes * 11 floats = 2816 floats = 704 float4 (704 = 2*256 + 192).
// ---------------------------------------------------------------------------
__global__ void k_dots(const float* __restrict__ x, int n) {
    __shared__ float sx[256 * 11];
    const int TILE_F4 = (256 * 11) / 4;       // 704
    int t = threadIdx.x;
    int base = blockIdx.x * (256 * 11);
    int lim = n * 11 - base;                  // valid floats in this tile
    if (lim >= 256 * 11) {
        const float4* xv4 = (const float4*)(x + base);
        float4* sx4 = (float4*)sx;
        sx4[t]       = xv4[t];
        sx4[t + 256] = xv4[t + 256];
        if (t + 512 < TILE_F4) sx4[t + 512] = xv4[t + 512];
    } else {
        for (int j = t; j < 256 * 11; j += 256)
            sx[j] = (j < lim) ? x[base + j] : 0.f;
    }
    __syncthreads();

    int v = blockIdx.x * 256 + t;
    if (v < n) {
        float a = 0.f, b = 0.f, g = 0.f, d = 0.f;
#pragma unroll
        for (int i = 0; i < 11; i++) {
            float xv = sx[t * 11 + i];
            a += xv * gP.p2[i];
            b += xv * gP.q2[i];
            g += xv * gP.p1[i];
            d += xv * gP.q1[i];
        }
        g_alpha[v] = a;
        g_bg[v]    = make_float2(b, g);
        g_delta[v] = d;
        g_agg[v]   = make_float2(0.f, 0.f);
        g_aggs[v]  = 0.f;
        if (v < GMAX) g_outmax[v] = ENC_NEG_INF;
    }
}

// ---------------------------------------------------------------------------
// K3: edge pass 1 — 2 edges/thread. Reads indices (int64 or int32) with
// 128-/64-bit loads, writes packed int32 (s,d) pairs for pass 2, gathers
// alpha, and does a float2 RED (sum_alpha, deg) per edge.
// ---------------------------------------------------------------------------
__global__ void k_edge1(const void* __restrict__ ei, int E) {
    int i = blockIdx.x * blockDim.x + threadIdx.x;
    int e0 = 2 * i;
    if (e0 >= E) return;
    int s0, s1, d0, d1;
    bool two = (e0 + 1 < E);
    if (g_flag) {
        const long long* p = (const long long*)ei;
        if (two) {
            longlong2 sv = *(const longlong2*)(p + e0);
            longlong2 dv = *(const longlong2*)(p + E + e0);
            s0 = (int)sv.x; s1 = (int)sv.y; d0 = (int)dv.x; d1 = (int)dv.y;
        } else {
            s0 = (int)p[e0]; d0 = (int)p[E + e0]; s1 = s0; d1 = -1;
        }
    } else {
        const int* p = (const int*)ei;
        if (two) {
            int2 sv = *(const int2*)(p + e0);
            int2 dv = *(const int2*)(p + E + e0);
            s0 = sv.x; s1 = sv.y; d0 = dv.x; d1 = dv.y;
        } else {
            s0 = p[e0]; d0 = p[E + e0]; s1 = s0; d1 = -1;
        }
    }
    g_eidx[i] = make_int4(s0, d0, s1, d1);

    float a0 = g_alpha[s0];
    if (two) {
        float a1 = g_alpha[s1];
        if (d0 == d1) {
            atomicAdd(&g_agg[d0], make_float2(a0 + a1, 2.f));
        } else {
            atomicAdd(&g_agg[d0], make_float2(a0, 1.f));
            atomicAdd(&g_agg[d1], make_float2(a1, 1.f));
        }
    } else {
        atomicAdd(&g_agg[d0], make_float2(a0, 1.f));
    }
}

// ---------------------------------------------------------------------------
// K4: per-node w = beta + s, where s = gamma + inv*sum_alpha + ps (deg>0) else s0
// ---------------------------------------------------------------------------
__global__ void k_nodes(int n) {
    int v = blockIdx.x * blockDim.x + threadIdx.x;
    if (v >= n) return;
    float2 ag = g_agg[v];
    float2 bg = g_bg[v];
    float s;
    if (ag.y > 0.f) {
        s = bg.y + (1.f / ag.y) * ag.x + gP.ps;
    } else {
        s = gP.s0;
    }
    g_w[v] = bg.x + s;
}

// ---------------------------------------------------------------------------
// K5: edge pass 2 — 2 edges/thread from packed int32 pairs (L2-resident),
// one scalar RED per edge: aggs[dst] += w[src]
// ---------------------------------------------------------------------------
__global__ void k_edge2(int E) {
    int i = blockIdx.x * blockDim.x + threadIdx.x;
    if (2 * i >= E) return;
    int4 p = g_eidx[i];
    float w0 = g_w[p.x];
    if (p.w >= 0) {
        float w1 = g_w[p.z];
        if (p.y == p.w) {
            atomicAdd(&g_aggs[p.y], w0 + w1);
        } else {
            atomicAdd(&g_aggs[p.y], w0);
            atomicAdd(&g_aggs[p.w], w1);
        }
    } else {
        atomicAdd(&g_aggs[p.y], w0);
    }
}

// ---------------------------------------------------------------------------
// K6: node_out + block-local segment max + global atomicMax (encoded)
// ---------------------------------------------------------------------------
__global__ void k_final(const void* __restrict__ batch, int n) {
    __shared__ unsigned sm[GMAX];
    int t = threadIdx.x;
    if (t < GMAX) sm[t] = ENC_NEG_INF;
    __syncthreads();
    int v = blockIdx.x * blockDim.x + t;
    if (v < n) {
        float deg = g_agg[v].y;
        float no;
        if (deg > 0.f) {
            no = g_delta[v] + gP.qs + gP.b2 + (1.f / deg) * g_aggs[v];
        } else {
            no = gP.bo;
        }
        int g = g_flag ? (int)((const long long*)batch)[v] : ((const int*)batch)[v];
        atomicMax(&sm[g], enc_f(no));
    }
    __syncthreads();
    if (t < GMAX && sm[t] != ENC_NEG_INF) atomicMax(&g_outmax[t], sm[t]);
}

// ---------------------------------------------------------------------------
// K7: decode out
// ---------------------------------------------------------------------------
__global__ void k_writeout(float* out, int g) {
    int i = threadIdx.x;
    if (i < g) out[i] = dec_f(g_outmax[i]);
}

extern "C" void kernel_launch(void* const* d_in, const int* in_sizes, int n_in,
                              void* d_out, int out_size) {
    const float* x     = (const float*)d_in[0];
    const void*  ei    = d_in[1];
    const void*  batch = d_in[2];
    const float* Wv  = (const float*)d_in[3];
    const float* bv  = (const float*)d_in[4];
    const float* We1 = (const float*)d_in[5];
    const float* be1 = (const float*)d_in[6];
    const float* Wx  = (const float*)d_in[7];
    const float* bx  = (const float*)d_in[8];
    const float* We2 = (const float*)d_in[9];
    const float* be2 = (const float*)d_in[10];
    const float* Wo  = (const float*)d_in[11];
    const float* bo  = (const float*)d_in[12];
    float* out = (float*)d_out;

    int n = in_sizes[0] / 11;   // 100000
    int E = in_sizes[1] / 2;    // 1600000
    if (n > NMAX) n = NMAX;
    if (E > 2 * EMAXH) E = 2 * EMAXH;

    const int TPB = 256;
    int nb_n = (n + TPB - 1) / TPB;
    int nb_e = ((E + 1) / 2 + TPB - 1) / TPB;

    k_fold<<<1, 256>>>(Wv, bv, We1, be1, Wx, bx, We2, be2, Wo, bo,
                       (const unsigned*)ei);
    k_dots<<<nb_n, TPB>>>(x, n);
    k_edge1<<<nb_e, TPB>>>(ei, E);
    k_nodes<<<nb_n, TPB>>>(n);
    k_edge2<<<nb_e, TPB>>>(E);
    k_final<<<nb_n, TPB>>>(batch, n);
    k_writeout<<<1, 64>>>(out, out_size);
}